// round 15
// baseline (speedup 1.0000x reference)
#include <cuda_runtime.h>
#include <cfloat>
#include <math.h>

#define BB 4096
#define V_SC 8000
#define SS 8
#define V_COMPO 2000
#define KK 10

// Allocation-free scratch (device globals)
__device__ float g_topv[BB * SS * KK];   // compo per-step top-k log_softmax scores
__device__ int   g_topi[BB * SS * KK];   // compo per-step top-k indices
__device__ int   g_sclab[BB * KK];       // sc top-k labels

// top_k ordering: larger value first; ties -> smaller index first (XLA CPU & GPU)
__device__ __forceinline__ bool better(float v1, int i1, float v2, int i2) {
    return (v1 > v2) || (v1 == v2 && i1 < i2);
}

// ---------------- sc top-k (raw logits; verified bitwise exact) ----------------
template <int BLK, int VLEN>
__global__ void topk_sc_kernel(const float* __restrict__ logits) {
    const int row = blockIdx.x;
    const int t = threadIdx.x;
    const float4* src =
        reinterpret_cast<const float4*>(logits + (size_t)row * VLEN);
    constexpr int N4 = VLEN / 4;

    float v[KK];
    int   id[KK];
#pragma unroll
    for (int p = 0; p < KK; p++) { v[p] = -FLT_MAX; id[p] = 0x7FFFFFFF; }

    for (int q = t; q < N4; q += BLK) {
        float4 x = src[q];
        float xv[4] = {x.x, x.y, x.z, x.w};
#pragma unroll
        for (int l = 0; l < 4; l++) {
            float cv = xv[l];
            int   ci = q * 4 + l;
            if (better(cv, ci, v[KK - 1], id[KK - 1])) {
#pragma unroll
                for (int p = 0; p < KK; p++) {
                    if (better(cv, ci, v[p], id[p])) {
                        float tv_ = v[p]; int ti_ = id[p];
                        v[p] = cv; id[p] = ci;
                        cv = tv_; ci = ti_;
                    }
                }
            }
        }
    }

    __shared__ float sv[BLK * KK];
    __shared__ int   si[BLK * KK];
#pragma unroll
    for (int p = 0; p < KK; p++) { sv[t * KK + p] = v[p]; si[t * KK + p] = id[p]; }
    __syncthreads();

    for (int stride = BLK / 2; stride > 0; stride >>= 1) {
        if (t < stride) {
            const int a0 = t * KK, b0 = (t + stride) * KK;
            float rv[KK]; int ri[KK];
            int pa = 0, pb = 0;
#pragma unroll
            for (int o = 0; o < KK; o++) {
                float va = sv[a0 + pa]; int ia = si[a0 + pa];
                float vb = sv[b0 + pb]; int ib = si[b0 + pb];
                bool ta = better(va, ia, vb, ib);
                rv[o] = ta ? va : vb;
                ri[o] = ta ? ia : ib;
                pa += ta ? 1 : 0;
                pb += ta ? 0 : 1;
            }
#pragma unroll
            for (int o = 0; o < KK; o++) { sv[a0 + o] = rv[o]; si[a0 + o] = ri[o]; }
        }
        __syncthreads();
    }

    if (t < KK) g_sclab[(size_t)row * KK + t] = si[t];
}

// ------- compo: XLA-CPU (LLVM VF4xIC4 = 16-accumulator) log_softmax + top-k -------
// One 512-thread block per (b,s) row. Sum order emulates LLVM's loop-vectorized
// fp32 reduction on aarch64 (Neoverse V2: VF=4, IC=4):
//   residue accumulators a_r = sum_q e[16q + r], r = 0..15, q sequential (125 iters)
//   part p (lanes 4p..4p+3) chain-combined: W_l = ((a_l + a_{l+4}) + a_{l+8}) + a_{l+12}
//   fast horizontal over 4 lanes: S = (W_0 + W_2) + (W_1 + W_3)
// exp/log emulated as correctly-rounded float via double (matches glibc's
// <=0.502-ulp expf/logf bits essentially always). Scores: fl(fl(x-max)-L).
// Ties in top-10: smaller index first (confirmed by the R14 probe).
__global__ void compo_kernel(const float* __restrict__ logits) {
    constexpr int BLK = 512;
    constexpr int TPK = 128;             // threads used for the top-k phase
    const int row = blockIdx.x;          // 0 .. BB*SS-1
    const int t = threadIdx.x;

    __shared__ float sx[V_COMPO];
    __shared__ float se[V_COMPO];
    __shared__ float sredf[BLK];
    __shared__ float sacc[16];
    __shared__ float sL;
    __shared__ float sv[TPK * KK];
    __shared__ int   si[TPK * KK];

    // coalesced vectorized row load into smem
    {
        const float4* src =
            reinterpret_cast<const float4*>(logits + (size_t)row * V_COMPO);
        float4* dst = reinterpret_cast<float4*>(sx);
        for (int q = t; q < V_COMPO / 4; q += BLK) dst[q] = src[q];
    }
    __syncthreads();

    // row max (order-independent, bitwise exact)
    float m = -FLT_MAX;
    for (int i = t; i < V_COMPO; i += BLK) m = fmaxf(m, sx[i]);
    sredf[t] = m;
    __syncthreads();
    for (int s = BLK / 2; s > 0; s >>= 1) {
        if (t < s) sredf[t] = fmaxf(sredf[t], sredf[t + s]);
        __syncthreads();
    }
    const float rmax = sredf[0];
    __syncthreads();

    // per-element exp (CR float via double) into smem
    for (int i = t; i < V_COMPO; i += BLK) {
        float sh = sx[i] - rmax;                 // f32 sub, as in reference
        se[i] = (float)exp((double)sh);          // correctly-rounded float exp
    }
    __syncthreads();

    // 16 residue accumulators, strictly sequential per residue (2000 = 16*125)
    if (t < 16) {
        float acc = 0.0f;
        for (int q = 0; q < V_COMPO / 16; q++) acc += se[16 * q + t];
        sacc[t] = acc;
    }
    __syncthreads();
    if (t == 0) {
        // chain-combine interleaved parts, lanewise
        float W[4];
#pragma unroll
        for (int l = 0; l < 4; l++)
            W[l] = ((sacc[l] + sacc[l + 4]) + sacc[l + 8]) + sacc[l + 12];
        // fast 4-lane horizontal reduce
        const float S = (W[0] + W[2]) + (W[1] + W[3]);
        sL = (float)log((double)S);              // correctly-rounded float log
    }
    __syncthreads();
    const float L = sL;

    // top-10 on scores fl(fl(x - max) - L); ties -> smaller index first
    float v[KK];
    int   id[KK];
#pragma unroll
    for (int p = 0; p < KK; p++) { v[p] = -FLT_MAX; id[p] = 0x7FFFFFFF; }

    if (t < TPK) {
        for (int i = t; i < V_COMPO; i += TPK) {
            float cv = (sx[i] - rmax) - L;
            int   ci = i;
            if (better(cv, ci, v[KK - 1], id[KK - 1])) {
#pragma unroll
                for (int p = 0; p < KK; p++) {
                    if (better(cv, ci, v[p], id[p])) {
                        float tv_ = v[p]; int ti_ = id[p];
                        v[p] = cv; id[p] = ci;
                        cv = tv_; ci = ti_;
                    }
                }
            }
        }
#pragma unroll
        for (int p = 0; p < KK; p++) { sv[t * KK + p] = v[p]; si[t * KK + p] = id[p]; }
    }
    __syncthreads();

    for (int stride = TPK / 2; stride > 0; stride >>= 1) {
        if (t < stride) {
            const int a0 = t * KK, b0 = (t + stride) * KK;
            float rv[KK]; int ri[KK];
            int pa = 0, pb = 0;
#pragma unroll
            for (int o = 0; o < KK; o++) {
                float va = sv[a0 + pa]; int ia = si[a0 + pa];
                float vb = sv[b0 + pb]; int ib = si[b0 + pb];
                bool ta = better(va, ia, vb, ib);
                rv[o] = ta ? va : vb;
                ri[o] = ta ? ia : ib;
                pa += ta ? 1 : 0;
                pb += ta ? 0 : 1;
            }
#pragma unroll
            for (int o = 0; o < KK; o++) { sv[a0 + o] = rv[o]; si[a0 + o] = ri[o]; }
        }
        __syncthreads();
    }

    if (t < KK) {
        g_topv[(size_t)row * KK + t] = sv[t];
        g_topi[(size_t)row * KK + t] = si[t];
    }
}

__global__ void zero_kernel(float* __restrict__ out, int n) {
    int i = blockIdx.x * blockDim.x + threadIdx.x;
    const int stride = gridDim.x * blockDim.x;
    for (; i < n; i += stride) out[i] = 0.0f;
}

// Beam search (k^2 expansion, top-k keep) + output assembly. Pure fp32 adds —
// identical op sequence to the reference; ties -> smallest linear coord.
__global__ void beam_assemble_kernel(const int* __restrict__ struc_raw,
                                     float* __restrict__ out,
                                     int lab_off, int seq_off, int res_off) {
    const int b = blockIdx.x * blockDim.x + threadIdx.x;
    if (b >= BB) return;

    const float* tv = g_topv + (size_t)b * SS * KK;
    const int*   ti = g_topi + (size_t)b * SS * KK;

    float scr[KK];
    int   seq[KK][SS];
#pragma unroll
    for (int j = 0; j < KK; j++) {
        scr[j] = tv[j];
        seq[j][0] = ti[j];
#pragma unroll
        for (int s = 1; s < SS; s++) seq[j][s] = 0;
    }

    for (int i = 1; i < SS; i++) {
        float sv2[KK]; int si2[KK];
#pragma unroll
        for (int c = 0; c < KK; c++) { sv2[c] = tv[i * KK + c]; si2[c] = ti[i * KK + c]; }

        float comb[KK * KK];
        for (int j = 0; j < KK; j++)
            for (int c = 0; c < KK; c++)
                comb[j * KK + c] = scr[j] + sv2[c];

        float nscr[KK];
        int   nseq[KK][SS];
        for (int r = 0; r < KK; r++) {
            float bv = -FLT_MAX; int bq = 0;
            for (int q = 0; q < KK * KK; q++) {
                if (comb[q] > bv) { bv = comb[q]; bq = q; }  // strict >: smallest coord wins ties
            }
            nscr[r] = bv;
            const int rr = bq / KK;
            const int cc = bq - rr * KK;
            for (int s = 0; s < SS; s++) nseq[r][s] = seq[rr][s];
            nseq[r][i] = si2[cc];
            comb[bq] = -FLT_MAX;
        }
        for (int j = 0; j < KK; j++) {
            scr[j] = nscr[j];
            for (int s = 0; s < SS; s++) seq[j][s] = nseq[j][s];
        }
    }

    // Tolerant decode of pred_char_struc (int32 0/1 or float32 0.0/1.0)
    int st;
    {
        const int raw = struc_raw[b];
        if (raw == 0)               st = 0;
        else if (raw == 1)          st = 1;
        else {
            const float f = __int_as_float(raw);
            st = (f == 1.0f) ? 1 : (f == 0.0f ? 0 : 2);
        }
    }

    for (int j = 0; j < KK; j++) {
        const int lab = g_sclab[b * KK + j];
        if (lab_off >= 0) out[lab_off + b * KK + j] = (float)lab;
        const int base = (b * KK + j) * SS;
        for (int s = 0; s < SS; s++) {
            const int sval = seq[j][s];
            if (seq_off >= 0) out[seq_off + base + s] = (float)sval;
            int rv;
            if (st == 0)      rv = (s == 0) ? lab : 0;
            else if (st == 1) rv = sval;
            else              rv = 0;
            if (res_off >= 0) out[res_off + base + s] = (float)rv;
        }
    }
}

extern "C" void kernel_launch(void* const* d_in, const int* in_sizes, int n_in,
                              void* d_out, int out_size) {
    const int*   p_struc = nullptr;
    const float* p_sc    = nullptr;
    const float* p_compo = nullptr;
    for (int i = 0; i < n_in; i++) {
        if (in_sizes[i] == BB)                     p_struc = (const int*)d_in[i];
        else if (in_sizes[i] == BB * V_SC)         p_sc    = (const float*)d_in[i];
        else if (in_sizes[i] == BB * SS * V_COMPO) p_compo = (const float*)d_in[i];
    }
    if (!p_struc && n_in > 0) p_struc = (const int*)d_in[0];
    if (!p_sc    && n_in > 1) p_sc    = (const float*)d_in[1];
    if (!p_compo && n_in > 2) p_compo = (const float*)d_in[2];
    if (!p_struc || !p_sc || !p_compo) return;

    float* out = (float*)d_out;

    const int n_lab = BB * KK;            // 40960
    const int n_seq = BB * KK * SS;       // 327680
    int lab_off = -1, seq_off = -1, res_off = -1;
    if (out_size >= n_lab + 2 * n_seq) {
        lab_off = 0; seq_off = n_lab; res_off = n_lab + n_seq;
    } else if (out_size >= 2 * n_seq) {
        seq_off = 0; res_off = n_seq;
    } else if (out_size >= n_seq) {
        res_off = 0;
    } else if (out_size >= n_lab) {
        lab_off = 0;
    }

    {
        int blocks = (out_size + 1023) / 1024;
        if (blocks > 1024) blocks = 1024;
        if (blocks > 0) zero_kernel<<<blocks, 256>>>(out, out_size);
    }
    // 1) sc top-10 labels (131 MB read)
    topk_sc_kernel<256, V_SC><<<BB, 256>>>(p_sc);
    // 2) compo log_softmax (XLA-CPU 16-accumulator order L) + per-(b,s) top-10
    compo_kernel<<<BB * SS, 512>>>(p_compo);
    // 3) beam search + assembly (tiny)
    beam_assemble_kernel<<<(BB + 127) / 128, 128>>>(p_struc, out,
                                                    lab_off, seq_off, res_off);
}

// round 16
// speedup vs baseline: 1.2670x; 1.2670x over previous
#include <cuda_runtime.h>
#include <cfloat>
#include <math.h>

#define BB 4096
#define V_SC 8000
#define SS 8
#define V_COMPO 2000
#define KK 10

// Allocation-free scratch (device globals)
__device__ float g_topv[BB * SS * KK];   // compo per-step top-k log_softmax scores
__device__ int   g_topi[BB * SS * KK];   // compo per-step top-k indices
__device__ int   g_sclab[BB * KK];       // sc top-k labels

// top_k ordering: larger value first; ties -> smaller index first
__device__ __forceinline__ bool better(float v1, int i1, float v2, int i2) {
    return (v1 > v2) || (v1 == v2 && i1 < i2);
}

// ---------------- sc top-k (raw logits; verified bitwise exact) ----------------
template <int BLK, int VLEN>
__global__ void topk_sc_kernel(const float* __restrict__ logits) {
    const int row = blockIdx.x;
    const int t = threadIdx.x;
    const float4* src =
        reinterpret_cast<const float4*>(logits + (size_t)row * VLEN);
    constexpr int N4 = VLEN / 4;

    float v[KK];
    int   id[KK];
#pragma unroll
    for (int p = 0; p < KK; p++) { v[p] = -FLT_MAX; id[p] = 0x7FFFFFFF; }

    for (int q = t; q < N4; q += BLK) {
        float4 x = src[q];
        float xv[4] = {x.x, x.y, x.z, x.w};
#pragma unroll
        for (int l = 0; l < 4; l++) {
            float cv = xv[l];
            int   ci = q * 4 + l;
            if (better(cv, ci, v[KK - 1], id[KK - 1])) {
#pragma unroll
                for (int p = 0; p < KK; p++) {
                    if (better(cv, ci, v[p], id[p])) {
                        float tv_ = v[p]; int ti_ = id[p];
                        v[p] = cv; id[p] = ci;
                        cv = tv_; ci = ti_;
                    }
                }
            }
        }
    }

    __shared__ float sv[BLK * KK];
    __shared__ int   si[BLK * KK];
#pragma unroll
    for (int p = 0; p < KK; p++) { sv[t * KK + p] = v[p]; si[t * KK + p] = id[p]; }
    __syncthreads();

    for (int stride = BLK / 2; stride > 0; stride >>= 1) {
        if (t < stride) {
            const int a0 = t * KK, b0 = (t + stride) * KK;
            float rv[KK]; int ri[KK];
            int pa = 0, pb = 0;
#pragma unroll
            for (int o = 0; o < KK; o++) {
                float va = sv[a0 + pa]; int ia = si[a0 + pa];
                float vb = sv[b0 + pb]; int ib = si[b0 + pb];
                bool ta = better(va, ia, vb, ib);
                rv[o] = ta ? va : vb;
                ri[o] = ta ? ia : ib;
                pa += ta ? 1 : 0;
                pb += ta ? 0 : 1;
            }
#pragma unroll
            for (int o = 0; o < KK; o++) { sv[a0 + o] = rv[o]; si[a0 + o] = ri[o]; }
        }
        __syncthreads();
    }

    if (t < KK) g_sclab[(size_t)row * KK + t] = si[t];
}

// Fast correctly-rounded float exp via lean double path (~9 fp64 ops).
// n = rint(16 x / ln2); r = x - n*(ln2/16), |r| <= ln2/32 = 0.02166.
// deg-6 double Horner: rel err ~4.4e-16 << float rounding boundary scale.
// Result = poly * 2^(n&15 /16) * 2^(n>>4)  (last factor via exponent-bits add).
__device__ __forceinline__ float exp_cr(float xf, const double* __restrict__ stab) {
    float kf = rintf(xf * 23.08312065422343f);      // 16/ln2
    int n = (int)kf;
    double r = fma((double)n, -4.33216987849965818386e-2, (double)xf); // ln2/16
    double p = 1.0 / 720.0;
    p = fma(p, r, 1.0 / 120.0);
    p = fma(p, r, 1.0 / 24.0);
    p = fma(p, r, 1.0 / 6.0);
    p = fma(p, r, 0.5);
    p = fma(p, r, 1.0);
    p = fma(p, r, 1.0);
    double e = p * stab[n & 15];
    long long bits = __double_as_longlong(e) + ((long long)(n >> 4) << 52);
    return (float)__longlong_as_double(bits);
}

// ------- compo: XLA-CPU (LLVM VF4xIC4 = 16-accumulator) log_softmax + top-k -------
// Bit-exact recipe (verified rel_err = 0): CR float exp per element; 16 residue
// fp32 accumulators a_r = seq-sum of e[16q+r]; W_l = ((a_l+a_{l+4})+a_{l+8})+a_{l+12};
// S = (W_0+W_2)+(W_1+W_3); L = CR float log(S). Scores fl(fl(x-max)-L);
// top-10 ties -> smaller index.
__global__ void compo_kernel(const float* __restrict__ logits) {
    constexpr int BLK = 512;
    constexpr int TPK = 256;             // threads used for the top-k phase
    const int row = blockIdx.x;          // 0 .. BB*SS-1
    const int t = threadIdx.x;

    __shared__ float  sx[V_COMPO];
    __shared__ float  se[V_COMPO];
    __shared__ float  sredf[BLK];
    __shared__ double stab[16];
    __shared__ float  sacc[16];
    __shared__ float  sL;
    __shared__ float  sv[TPK * KK];
    __shared__ int    si[TPK * KK];

    // build 2^(j/16) table (CR doubles from libdevice exp2; deterministic)
    if (t < 16) stab[t] = exp2((double)t * 0.0625);

    // coalesced vectorized row load into smem
    {
        const float4* src =
            reinterpret_cast<const float4*>(logits + (size_t)row * V_COMPO);
        float4* dst = reinterpret_cast<float4*>(sx);
        for (int q = t; q < V_COMPO / 4; q += BLK) dst[q] = src[q];
    }
    __syncthreads();

    // row max (order-independent, bitwise exact)
    float m = -FLT_MAX;
    for (int i = t; i < V_COMPO; i += BLK) m = fmaxf(m, sx[i]);
    sredf[t] = m;
    __syncthreads();
    for (int s = BLK / 2; s > 0; s >>= 1) {
        if (t < s) sredf[t] = fmaxf(sredf[t], sredf[t + s]);
        __syncthreads();
    }
    const float rmax = sredf[0];
    __syncthreads();

    // per-element CR exp into smem (lean double path)
    for (int i = t; i < V_COMPO; i += BLK) {
        float sh = sx[i] - rmax;                 // f32 sub, as in reference
        se[i] = exp_cr(sh, stab);
    }
    __syncthreads();

    // 16 residue accumulators, strictly sequential per residue (2000 = 16*125)
    if (t < 16) {
        float acc = 0.0f;
        for (int q = 0; q < V_COMPO / 16; q++) acc += se[16 * q + t];
        sacc[t] = acc;
    }
    __syncthreads();
    if (t == 0) {
        float W[4];
#pragma unroll
        for (int l = 0; l < 4; l++)
            W[l] = ((sacc[l] + sacc[l + 4]) + sacc[l + 8]) + sacc[l + 12];
        const float S = (W[0] + W[2]) + (W[1] + W[3]);
        sL = (float)log((double)S);              // correctly-rounded float log
    }
    __syncthreads();
    const float L = sL;

    // top-10 on scores fl(fl(x - max) - L); ties -> smaller index first
    float v[KK];
    int   id[KK];
#pragma unroll
    for (int p = 0; p < KK; p++) { v[p] = -FLT_MAX; id[p] = 0x7FFFFFFF; }

    if (t < TPK) {
        for (int i = t; i < V_COMPO; i += TPK) {
            float cv = (sx[i] - rmax) - L;
            int   ci = i;
            if (better(cv, ci, v[KK - 1], id[KK - 1])) {
#pragma unroll
                for (int p = 0; p < KK; p++) {
                    if (better(cv, ci, v[p], id[p])) {
                        float tv_ = v[p]; int ti_ = id[p];
                        v[p] = cv; id[p] = ci;
                        cv = tv_; ci = ti_;
                    }
                }
            }
        }
#pragma unroll
        for (int p = 0; p < KK; p++) { sv[t * KK + p] = v[p]; si[t * KK + p] = id[p]; }
    }
    __syncthreads();

    for (int stride = TPK / 2; stride > 0; stride >>= 1) {
        if (t < stride) {
            const int a0 = t * KK, b0 = (t + stride) * KK;
            float rv[KK]; int ri[KK];
            int pa = 0, pb = 0;
#pragma unroll
            for (int o = 0; o < KK; o++) {
                float va = sv[a0 + pa]; int ia = si[a0 + pa];
                float vb = sv[b0 + pb]; int ib = si[b0 + pb];
                bool ta = better(va, ia, vb, ib);
                rv[o] = ta ? va : vb;
                ri[o] = ta ? ia : ib;
                pa += ta ? 1 : 0;
                pb += ta ? 0 : 1;
            }
#pragma unroll
            for (int o = 0; o < KK; o++) { sv[a0 + o] = rv[o]; si[a0 + o] = ri[o]; }
        }
        __syncthreads();
    }

    if (t < KK) {
        g_topv[(size_t)row * KK + t] = sv[t];
        g_topi[(size_t)row * KK + t] = si[t];
    }
}

__global__ void zero_kernel(float* __restrict__ out, int n) {
    int i = blockIdx.x * blockDim.x + threadIdx.x;
    const int stride = gridDim.x * blockDim.x;
    for (; i < n; i += stride) out[i] = 0.0f;
}

// Beam search (k^2 expansion, top-k keep) + output assembly. Pure fp32 adds —
// identical op sequence to the reference; ties -> smallest linear coord.
__global__ void beam_assemble_kernel(const int* __restrict__ struc_raw,
                                     float* __restrict__ out,
                                     int lab_off, int seq_off, int res_off) {
    const int b = blockIdx.x * blockDim.x + threadIdx.x;
    if (b >= BB) return;

    const float* tv = g_topv + (size_t)b * SS * KK;
    const int*   ti = g_topi + (size_t)b * SS * KK;

    float scr[KK];
    int   seq[KK][SS];
#pragma unroll
    for (int j = 0; j < KK; j++) {
        scr[j] = tv[j];
        seq[j][0] = ti[j];
#pragma unroll
        for (int s = 1; s < SS; s++) seq[j][s] = 0;
    }

    for (int i = 1; i < SS; i++) {
        float sv2[KK]; int si2[KK];
#pragma unroll
        for (int c = 0; c < KK; c++) { sv2[c] = tv[i * KK + c]; si2[c] = ti[i * KK + c]; }

        float comb[KK * KK];
        for (int j = 0; j < KK; j++)
            for (int c = 0; c < KK; c++)
                comb[j * KK + c] = scr[j] + sv2[c];

        float nscr[KK];
        int   nseq[KK][SS];
        for (int r = 0; r < KK; r++) {
            float bv = -FLT_MAX; int bq = 0;
            for (int q = 0; q < KK * KK; q++) {
                if (comb[q] > bv) { bv = comb[q]; bq = q; }  // strict >: smallest coord wins ties
            }
            nscr[r] = bv;
            const int rr = bq / KK;
            const int cc = bq - rr * KK;
            for (int s = 0; s < SS; s++) nseq[r][s] = seq[rr][s];
            nseq[r][i] = si2[cc];
            comb[bq] = -FLT_MAX;
        }
        for (int j = 0; j < KK; j++) {
            scr[j] = nscr[j];
            for (int s = 0; s < SS; s++) seq[j][s] = nseq[j][s];
        }
    }

    // Tolerant decode of pred_char_struc (int32 0/1 or float32 0.0/1.0)
    int st;
    {
        const int raw = struc_raw[b];
        if (raw == 0)               st = 0;
        else if (raw == 1)          st = 1;
        else {
            const float f = __int_as_float(raw);
            st = (f == 1.0f) ? 1 : (f == 0.0f ? 0 : 2);
        }
    }

    for (int j = 0; j < KK; j++) {
        const int lab = g_sclab[b * KK + j];
        if (lab_off >= 0) out[lab_off + b * KK + j] = (float)lab;
        const int base = (b * KK + j) * SS;
        for (int s = 0; s < SS; s++) {
            const int sval = seq[j][s];
            if (seq_off >= 0) out[seq_off + base + s] = (float)sval;
            int rv;
            if (st == 0)      rv = (s == 0) ? lab : 0;
            else if (st == 1) rv = sval;
            else              rv = 0;
            if (res_off >= 0) out[res_off + base + s] = (float)rv;
        }
    }
}

extern "C" void kernel_launch(void* const* d_in, const int* in_sizes, int n_in,
                              void* d_out, int out_size) {
    const int*   p_struc = nullptr;
    const float* p_sc    = nullptr;
    const float* p_compo = nullptr;
    for (int i = 0; i < n_in; i++) {
        if (in_sizes[i] == BB)                     p_struc = (const int*)d_in[i];
        else if (in_sizes[i] == BB * V_SC)         p_sc    = (const float*)d_in[i];
        else if (in_sizes[i] == BB * SS * V_COMPO) p_compo = (const float*)d_in[i];
    }
    if (!p_struc && n_in > 0) p_struc = (const int*)d_in[0];
    if (!p_sc    && n_in > 1) p_sc    = (const float*)d_in[1];
    if (!p_compo && n_in > 2) p_compo = (const float*)d_in[2];
    if (!p_struc || !p_sc || !p_compo) return;

    float* out = (float*)d_out;

    const int n_lab = BB * KK;            // 40960
    const int n_seq = BB * KK * SS;       // 327680
    int lab_off = -1, seq_off = -1, res_off = -1;
    if (out_size >= n_lab + 2 * n_seq) {
        lab_off = 0; seq_off = n_lab; res_off = n_lab + n_seq;
    } else if (out_size >= 2 * n_seq) {
        seq_off = 0; res_off = n_seq;
    } else if (out_size >= n_seq) {
        res_off = 0;
    } else if (out_size >= n_lab) {
        lab_off = 0;
    }

    {
        int blocks = (out_size + 1023) / 1024;
        if (blocks > 1024) blocks = 1024;
        if (blocks > 0) zero_kernel<<<blocks, 256>>>(out, out_size);
    }
    // 1) sc top-10 labels (131 MB read)
    topk_sc_kernel<256, V_SC><<<BB, 256>>>(p_sc);
    // 2) compo log_softmax (bit-exact 16-acc order, fast CR exp) + top-10
    compo_kernel<<<BB * SS, 512>>>(p_compo);
    // 3) beam search + assembly (tiny)
    beam_assemble_kernel<<<(BB + 127) / 128, 128>>>(p_struc, out,
                                                    lab_off, seq_off, res_off);
}

// round 17
// speedup vs baseline: 2.3320x; 1.8406x over previous
#include <cuda_runtime.h>
#include <cfloat>
#include <math.h>

#define BB 4096
#define V_SC 8000
#define SS 8
#define V_COMPO 2000
#define KK 10

// Allocation-free scratch (device globals)
__device__ float g_topv[BB * SS * KK];
__device__ int   g_topi[BB * SS * KK];
__device__ int   g_sclab[BB * KK];
// exp constants: c1 (14-bit ln2/16), c2, c3 residuals, 16/ln2
__device__ float g_expc[4];
__device__ float g_tab_hi[16], g_tab_lo[16];

__device__ __forceinline__ bool better(float v1, int i1, float v2, int i2) {
    return (v1 > v2) || (v1 == v2 && i1 < i2);
}

// One-time constant builder (few fp64 ops per LAUNCH; deterministic)
__global__ void setup_kernel() {
    double c = log(2.0) / 16.0;
    float c1 = __double2float_rn(c);
    c1 = __int_as_float(__float_as_int(c1) & 0xFFFFFC00);  // 14-bit significand
    double rem = c - (double)c1;
    float c2 = (float)rem;
    float c3 = (float)(rem - (double)c2);
    g_expc[0] = c1; g_expc[1] = c2; g_expc[2] = c3;
    g_expc[3] = (float)(16.0 / log(2.0));
    for (int j = 0; j < 16; j++) {
        double v = exp2((double)j * 0.0625);
        float h = (float)v;
        g_tab_hi[j] = h;
        g_tab_lo[j] = (float)(v - (double)h);
    }
}

// Correctly-rounded float exp, PURE fp32 (double-float arithmetic), ~40 ops.
__device__ __forceinline__ float exp_crf(float sh, const float* __restrict__ cst,
                                         const float* __restrict__ th_,
                                         const float* __restrict__ tl_) {
    const float c1 = cst[0], c2 = cst[1], c3 = cst[2], klog2e = cst[3];
    float kf = rintf(sh * klog2e);
    int   n  = (int)kf;
    float t1 = fmaf(-kf, c1, sh);            // EXACT (c1 14-bit, |n|<=2^10)
    float t2 = -kf * c2;
    float t2e = fmaf(-kf, c2, -t2);          // exact product residual
    // TwoSum(t1, t2)
    float rh = t1 + t2;
    float zz = rh - t1;
    float rl = (t1 - (rh - zz)) + (t2 - zz);
    rl += t2e;
    rl = fmaf(-kf, c3, rl);
    // w(r) = 1/6 + r/24 + r^2/120 + r^3/720   (fp32 Horner)
    float w = fmaf(rh, 1.0f / 720.0f, 1.0f / 120.0f);
    w = fmaf(rh, w, 1.0f / 24.0f);
    w = fmaf(rh, w, 1.0f / 6.0f);
    // r^2 in dd
    float p2 = rh * rh;
    float e2 = fmaf(rh, rh, -p2);
    // B = r^2/2 + r^3*w in dd
    float h  = 0.5f * p2;
    float he = fmaf(rh, rl, 0.5f * e2);
    float tb = (p2 * rh) * w;
    float bh = h + tb;                        // Fast2Sum (|h| >= |tb|)
    float bl = (h - bh) + tb;
    bl += he;
    // A = 1 + r in dd (Fast2Sum, 1 >= |rh|)
    float ah = 1.0f + rh;
    float al = (1.0f - ah) + rh;
    al += rl;
    // C = A + B in dd (Fast2Sum, |ah| >= |bh|)
    float ch = ah + bh;
    float cl = ((ah - ch) + bh) + (al + bl);
    // C * table(j) in dd
    const int j = n & 15;
    float th = th_[j], tl = tl_[j];
    float m  = ch * th;
    float me = fmaf(ch, th, -m);
    me = fmaf(ch, tl, me);
    me = fmaf(cl, th, me);
    float ef = m + me;                        // the one CR rounding
    float s  = __int_as_float(((n >> 4) + 127) << 23);  // 2^(n>>4), exact
    return ef * s;
}

// ---------------- sc top-k (raw logits; verified bitwise exact) ----------------
template <int BLK, int VLEN>
__global__ void topk_sc_kernel(const float* __restrict__ logits) {
    const int row = blockIdx.x;
    const int t = threadIdx.x;
    const float4* src =
        reinterpret_cast<const float4*>(logits + (size_t)row * VLEN);
    constexpr int N4 = VLEN / 4;

    float v[KK];
    int   id[KK];
#pragma unroll
    for (int p = 0; p < KK; p++) { v[p] = -FLT_MAX; id[p] = 0x7FFFFFFF; }

    for (int q = t; q < N4; q += BLK) {
        float4 x = src[q];
        float xv[4] = {x.x, x.y, x.z, x.w};
#pragma unroll
        for (int l = 0; l < 4; l++) {
            float cv = xv[l];
            int   ci = q * 4 + l;
            if (better(cv, ci, v[KK - 1], id[KK - 1])) {
#pragma unroll
                for (int p = 0; p < KK; p++) {
                    if (better(cv, ci, v[p], id[p])) {
                        float tv_ = v[p]; int ti_ = id[p];
                        v[p] = cv; id[p] = ci;
                        cv = tv_; ci = ti_;
                    }
                }
            }
        }
    }

    __shared__ float sv[BLK * KK];
    __shared__ int   si[BLK * KK];
#pragma unroll
    for (int p = 0; p < KK; p++) { sv[t * KK + p] = v[p]; si[t * KK + p] = id[p]; }
    __syncthreads();

    for (int stride = BLK / 2; stride > 0; stride >>= 1) {
        if (t < stride) {
            const int a0 = t * KK, b0 = (t + stride) * KK;
            float rv[KK]; int ri[KK];
            int pa = 0, pb = 0;
#pragma unroll
            for (int o = 0; o < KK; o++) {
                float va = sv[a0 + pa]; int ia = si[a0 + pa];
                float vb = sv[b0 + pb]; int ib = si[b0 + pb];
                bool ta = better(va, ia, vb, ib);
                rv[o] = ta ? va : vb;
                ri[o] = ta ? ia : ib;
                pa += ta ? 1 : 0;
                pb += ta ? 0 : 1;
            }
#pragma unroll
            for (int o = 0; o < KK; o++) { sv[a0 + o] = rv[o]; si[a0 + o] = ri[o]; }
        }
        __syncthreads();
    }

    if (t < KK) g_sclab[(size_t)row * KK + t] = si[t];
}

// ------- compo: bit-exact XLA-CPU 16-acc log_softmax + top-k (fp32-only exp) -------
__global__ void compo_kernel(const float* __restrict__ logits) {
    constexpr int BLK = 512;
    constexpr int TPK = 256;
    const int row = blockIdx.x;
    const int t = threadIdx.x;

    __shared__ float sx[V_COMPO];
    __shared__ float se[V_COMPO];
    __shared__ float sredf[BLK];
    __shared__ float scst[4];
    __shared__ float sth[16], stl[16];
    __shared__ float sacc[16];
    __shared__ float sL;
    __shared__ float sv[TPK * KK];
    __shared__ int   si[TPK * KK];

    if (t < 16) { sth[t] = g_tab_hi[t]; stl[t] = g_tab_lo[t]; }
    if (t < 4)  scst[t] = g_expc[t];

    {
        const float4* src =
            reinterpret_cast<const float4*>(logits + (size_t)row * V_COMPO);
        float4* dst = reinterpret_cast<float4*>(sx);
        for (int q = t; q < V_COMPO / 4; q += BLK) dst[q] = src[q];
    }
    __syncthreads();

    // row max (order-independent)
    float m = -FLT_MAX;
    for (int i = t; i < V_COMPO; i += BLK) m = fmaxf(m, sx[i]);
    sredf[t] = m;
    __syncthreads();
    for (int s = BLK / 2; s > 0; s >>= 1) {
        if (t < s) sredf[t] = fmaxf(sredf[t], sredf[t + s]);
        __syncthreads();
    }
    const float rmax = sredf[0];
    __syncthreads();

    // per-element CR exp (pure fp32 path)
    for (int i = t; i < V_COMPO; i += BLK) {
        float sh = sx[i] - rmax;
        se[i] = exp_crf(sh, scst, sth, stl);
    }
    __syncthreads();

    // FROZEN bit-exact sum: 16 residue accumulators, sequential per residue
    if (t < 16) {
        float acc = 0.0f;
        for (int q = 0; q < V_COMPO / 16; q++) acc += se[16 * q + t];
        sacc[t] = acc;
    }
    __syncthreads();
    if (t == 0) {
        float W[4];
#pragma unroll
        for (int l = 0; l < 4; l++)
            W[l] = ((sacc[l] + sacc[l + 4]) + sacc[l + 8]) + sacc[l + 12];
        const float S = (W[0] + W[2]) + (W[1] + W[3]);
        sL = (float)log((double)S);   // one CR fp64 log per row (negligible)
    }
    __syncthreads();
    const float L = sL;

    // top-10 on fl(fl(x - max) - L); ties -> smaller index
    float v[KK];
    int   id[KK];
#pragma unroll
    for (int p = 0; p < KK; p++) { v[p] = -FLT_MAX; id[p] = 0x7FFFFFFF; }

    if (t < TPK) {
        for (int i = t; i < V_COMPO; i += TPK) {
            float cv = (sx[i] - rmax) - L;
            int   ci = i;
            if (better(cv, ci, v[KK - 1], id[KK - 1])) {
#pragma unroll
                for (int p = 0; p < KK; p++) {
                    if (better(cv, ci, v[p], id[p])) {
                        float tv_ = v[p]; int ti_ = id[p];
                        v[p] = cv; id[p] = ci;
                        cv = tv_; ci = ti_;
                    }
                }
            }
        }
#pragma unroll
        for (int p = 0; p < KK; p++) { sv[t * KK + p] = v[p]; si[t * KK + p] = id[p]; }
    }
    __syncthreads();

    for (int stride = TPK / 2; stride > 0; stride >>= 1) {
        if (t < stride) {
            const int a0 = t * KK, b0 = (t + stride) * KK;
            float rv[KK]; int ri[KK];
            int pa = 0, pb = 0;
#pragma unroll
            for (int o = 0; o < KK; o++) {
                float va = sv[a0 + pa]; int ia = si[a0 + pa];
                float vb = sv[b0 + pb]; int ib = si[b0 + pb];
                bool ta = better(va, ia, vb, ib);
                rv[o] = ta ? va : vb;
                ri[o] = ta ? ia : ib;
                pa += ta ? 1 : 0;
                pb += ta ? 0 : 1;
            }
#pragma unroll
            for (int o = 0; o < KK; o++) { sv[a0 + o] = rv[o]; si[a0 + o] = ri[o]; }
        }
        __syncthreads();
    }

    if (t < KK) {
        g_topv[(size_t)row * KK + t] = sv[t];
        g_topi[(size_t)row * KK + t] = si[t];
    }
}

__global__ void zero_kernel(float* __restrict__ out, int n) {
    int i = blockIdx.x * blockDim.x + threadIdx.x;
    const int stride = gridDim.x * blockDim.x;
    for (; i < n; i += stride) out[i] = 0.0f;
}

// Beam search + assembly (per-thread, spread over 128 blocks of 32)
__global__ void beam_assemble_kernel(const int* __restrict__ struc_raw,
                                     float* __restrict__ out,
                                     int lab_off, int seq_off, int res_off) {
    const int b = blockIdx.x * blockDim.x + threadIdx.x;
    if (b >= BB) return;

    const float* tv = g_topv + (size_t)b * SS * KK;
    const int*   ti = g_topi + (size_t)b * SS * KK;

    float scr[KK];
    int   seq[KK][SS];
#pragma unroll
    for (int j = 0; j < KK; j++) {
        scr[j] = tv[j];
        seq[j][0] = ti[j];
#pragma unroll
        for (int s = 1; s < SS; s++) seq[j][s] = 0;
    }

    for (int i = 1; i < SS; i++) {
        float sv2[KK]; int si2[KK];
#pragma unroll
        for (int c = 0; c < KK; c++) { sv2[c] = tv[i * KK + c]; si2[c] = ti[i * KK + c]; }

        float comb[KK * KK];
        for (int j = 0; j < KK; j++)
            for (int c = 0; c < KK; c++)
                comb[j * KK + c] = scr[j] + sv2[c];

        float nscr[KK];
        int   nseq[KK][SS];
        for (int r = 0; r < KK; r++) {
            float bv = -FLT_MAX; int bq = 0;
            for (int q = 0; q < KK * KK; q++) {
                if (comb[q] > bv) { bv = comb[q]; bq = q; }
            }
            nscr[r] = bv;
            const int rr = bq / KK;
            const int cc = bq - rr * KK;
            for (int s = 0; s < SS; s++) nseq[r][s] = seq[rr][s];
            nseq[r][i] = si2[cc];
            comb[bq] = -FLT_MAX;
        }
        for (int j = 0; j < KK; j++) {
            scr[j] = nscr[j];
            for (int s = 0; s < SS; s++) seq[j][s] = nseq[j][s];
        }
    }

    int st;
    {
        const int raw = struc_raw[b];
        if (raw == 0)               st = 0;
        else if (raw == 1)          st = 1;
        else {
            const float f = __int_as_float(raw);
            st = (f == 1.0f) ? 1 : (f == 0.0f ? 0 : 2);
        }
    }

    for (int j = 0; j < KK; j++) {
        const int lab = g_sclab[b * KK + j];
        if (lab_off >= 0) out[lab_off + b * KK + j] = (float)lab;
        const int base = (b * KK + j) * SS;
        for (int s = 0; s < SS; s++) {
            const int sval = seq[j][s];
            if (seq_off >= 0) out[seq_off + base + s] = (float)sval;
            int rv;
            if (st == 0)      rv = (s == 0) ? lab : 0;
            else if (st == 1) rv = sval;
            else              rv = 0;
            if (res_off >= 0) out[res_off + base + s] = (float)rv;
        }
    }
}

extern "C" void kernel_launch(void* const* d_in, const int* in_sizes, int n_in,
                              void* d_out, int out_size) {
    const int*   p_struc = nullptr;
    const float* p_sc    = nullptr;
    const float* p_compo = nullptr;
    for (int i = 0; i < n_in; i++) {
        if (in_sizes[i] == BB)                     p_struc = (const int*)d_in[i];
        else if (in_sizes[i] == BB * V_SC)         p_sc    = (const float*)d_in[i];
        else if (in_sizes[i] == BB * SS * V_COMPO) p_compo = (const float*)d_in[i];
    }
    if (!p_struc && n_in > 0) p_struc = (const int*)d_in[0];
    if (!p_sc    && n_in > 1) p_sc    = (const float*)d_in[1];
    if (!p_compo && n_in > 2) p_compo = (const float*)d_in[2];
    if (!p_struc || !p_sc || !p_compo) return;

    float* out = (float*)d_out;

    const int n_lab = BB * KK;
    const int n_seq = BB * KK * SS;
    int lab_off = -1, seq_off = -1, res_off = -1;
    if (out_size >= n_lab + 2 * n_seq) {
        lab_off = 0; seq_off = n_lab; res_off = n_lab + n_seq;
    } else if (out_size >= 2 * n_seq) {
        seq_off = 0; res_off = n_seq;
    } else if (out_size >= n_seq) {
        res_off = 0;
    } else if (out_size >= n_lab) {
        lab_off = 0;
    }

    setup_kernel<<<1, 1>>>();
    {
        int blocks = (out_size + 1023) / 1024;
        if (blocks > 1024) blocks = 1024;
        if (blocks > 0) zero_kernel<<<blocks, 256>>>(out, out_size);
    }
    topk_sc_kernel<256, V_SC><<<BB, 256>>>(p_sc);
    compo_kernel<<<BB * SS, 512>>>(p_compo);
    beam_assemble_kernel<<<128, 32>>>(p_struc, out, lab_off, seq_off, res_off);
}